// round 17
// baseline (speedup 1.0000x reference)
#include <cuda_runtime.h>
#include <cuda_fp16.h>
#include <cstring>

typedef unsigned long long u64;
typedef unsigned int u32;

#define KBOX   1024
#define NT2    4096          // 4096 tiles of 256 rows
#define GRID   304           // 152 SMs x 2 CTA/SM (GB300)
#define BF_STRIDE 260        // u32 per combo (64 chunks + 1 pad chunk)

// dynamic smem layout (bytes)
#define OFF_BF   0           // 32*260*4 = 33280
#define OFF_W1F  33280       // 4096
#define OFF_B2F  37376       // 4096 (b2 fragment table [pass][combo2][8])
#define OFF_FF   41472       // 8 warps * 288 uint2 = 18432 (feature tables)
#define OFF_STG  59904       // 8 warps * 1280 floats * 4 = 40960
#define SMEM_BYTES 100864
#define STG_WARP 1280        // floats per warp buffer (32 rows * 40)
#define STG_ROW  40          // floats per staged row (conflict-free padding)
#define FF_ROW   9           // uint2 per feature row (7 pairs + zero slot + pad)
#define FF_WARP  (32 * FF_ROW)

__device__ __forceinline__ u32 h2u(__half2 h) {
    u32 u; memcpy(&u, &h, 4); return u;
}
__device__ __forceinline__ u32 hmax2z(u32 v) {
    __half2 h; memcpy(&h, &v, 4);
    h = __hmax2(h, __half2half2(__ushort_as_half(0)));
    return h2u(h);
}

// m16n8k16 fp16 MMA, fp32 accum
__device__ __forceinline__ void mma16816(float* c, u32 a0, u32 a1, u32 a2, u32 a3,
                                         u32 b0, u32 b1) {
    asm volatile(
        "mma.sync.aligned.m16n8k16.row.col.f32.f16.f16.f32 "
        "{%0,%1,%2,%3}, {%4,%5,%6,%7}, {%8,%9}, {%0,%1,%2,%3};"
        : "+f"(c[0]), "+f"(c[1]), "+f"(c[2]), "+f"(c[3])
        : "r"(a0), "r"(a1), "r"(a2), "r"(a3), "r"(b0), "r"(b1));
}

extern "C" __global__ void __launch_bounds__(256, 2)
pair_mlp_hmma8(const float* __restrict__ boxes,
               const float* __restrict__ W1, const float* __restrict__ b1,
               const float* __restrict__ W2, const float* __restrict__ b2,
               float* __restrict__ out)
{
    extern __shared__ char smemraw[];
    u32*   Bf   = (u32*)(smemraw + OFF_BF);    // fragment-ordered W2
    u32*   W1f2 = (u32*)(smemraw + OFF_W1F);   // pair-fragment-ordered W1 (+bias)
    float* b2f  = (float*)(smemraw + OFF_B2F); // b2 fragment table
    uint2* ffbuf = (uint2*)(smemraw + OFF_FF); // per-warp feature tables
    float* stgbuf = (float*)(smemraw + OFF_STG);

    const int tid = threadIdx.x;
    const int w   = tid >> 5;
    const int l   = tid & 31;
    const int lp  = l & 3;           // k-pair group within fragment
    const int npos = l >> 2;         // n position within fragment
    const int combo2 = npos * 4 + lp;

    // ---- one-time setup ----
    // W2 fragment pack
    for (int idx = tid; idx < 8192; idx += 256) {
        const int cb  = idx >> 8;
        const int rest = idx & 255;
        const int s2  = rest >> 3;
        const int q   = rest & 7;
        const int c   = q >> 2;
        const int wd  = q & 3;
        const int pass = s2 >> 3, kt = s2 & 7;
        const int lp_  = cb & 3,  np_ = cb >> 2;
        const int kp  = 8 * kt + lp_ + 4 * c;
        const int n   = pass * 32 + wd * 8 + np_;
        const __half2 p = __floats2half2_rn(W2[(2 * kp) * 128 + n],
                                            W2[(2 * kp + 1) * 128 + n]);
        Bf[cb * BF_STRIDE + s2 * 8 + q] = h2u(p);
    }
    // W1 pack for LDS.128: [gp][lane][4] = {g=2gp:b0,b1, g=2gp+1:b0,b1}
    for (int idx = tid; idx < 1024; idx += 256) {
        const int gp = idx >> 7;
        const int rest = idx & 127;
        const int ll = rest >> 2;
        const int q  = rest & 3;
        const int g  = 2 * gp + (q >> 1);
        const int wh = q & 1;
        const int n  = 8 * g + (ll >> 2);
        const int k0 = 2 * (ll & 3) + 8 * wh;
        const int k1 = k0 + 1;
        float v0 = (k0 < 13) ? W1[k0 * 128 + n] : ((k0 == 13) ? b1[n] : 0.0f);
        float v1 = (k1 < 13) ? W1[k1 * 128 + n] : ((k1 == 13) ? b1[n] : 0.0f);
        W1f2[idx] = h2u(__floats2half2_rn(v0, v1));
    }
    // b2 fragment table
    for (int idx = tid; idx < 1024; idx += 256) {
        const int pass = idx >> 8;
        const int rest = idx & 255;
        const int cb   = rest >> 3;
        const int k    = rest & 7;
        const int nt   = k >> 1;
        const int tt   = k & 1;
        const int lp_  = cb & 3;
        b2f[idx] = b2[pass * 32 + nt * 8 + lp_ * 2 + tt];
    }
    __syncthreads();

    const u32* bcombo = Bf + combo2 * BF_STRIDE;
    float* mybuf = stgbuf + w * STG_WARP;
    uint2* myff  = ffbuf + w * FF_WARP;
    const float* myb2f = b2f + combo2 * 8;
    const int colblk = (l & 7) * 4;       // epilogue drain column block
    const int rsub   = l >> 3;            // epilogue drain row sub-index

    // permanent zero slot (slot 7): phase 1a only writes slots 0..6, so this
    // survives all tiles and makes the lp==3 upper-fragment gather branch-free
    myff[l * FF_ROW + 7] = make_uint2(0u, 0u);

    // ---- phase 1a as a macro: pair features for one row per lane -> table ----
#define PHASE1A(T2) do {                                                        \
        const int i2  = (T2) >> 2;                                              \
        const int jw2 = (((T2) & 3) << 8) + w * 32;                             \
        const float4 Bi = __ldg((const float4*)boxes + i2);                     \
        const float4 Bj = __ldg((const float4*)boxes + (jw2 + l));              \
        const float xi = Bi.x, yi = Bi.y, wi = Bi.z, hi_ = Bi.w;                \
        const float xj = Bj.x, yj = Bj.y, wj = Bj.z, hj = Bj.w;                 \
        const float rwi = 1.0f / wi, rhi = 1.0f / hi_;                          \
        const float dx = (xj - xi) * rwi;                                       \
        const float dy = (yj - yi) * rhi;                                       \
        const float dw = __logf(wj * rwi + 1e-6f);                              \
        const float dh = __logf(hj * rhi + 1e-6f);                              \
        const float iw = fmaxf(0.0f, fminf(xi + wi, xj + wj) - fmaxf(xi, xj));  \
        const float ih = fmaxf(0.0f, fminf(yi + hi_, yj + hj) - fmaxf(yi, yj)); \
        const float inter = iw * ih;                                            \
        const float uni   = wi * hi_ + wj * hj - inter;                         \
        const float iou   = inter / (uni + 1e-6f);                              \
        const float2 pr[7] = {                                                  \
            {dx, dy}, {dw, dh}, {wi, hi_}, {wj, hj},                            \
            {iou, xi}, {yi, xj}, {yj, 1.0f}                                     \
        };                                                                      \
        _Pragma("unroll")                                                       \
        for (int p = 0; p < 7; p++) {                                           \
            const __half2 hh = __floats2half2_rn(pr[p].x, pr[p].y);             \
            const float2 hf = __half22float2(hh);                               \
            const __half2 ll2 = __floats2half2_rn(pr[p].x - hf.x, pr[p].y - hf.y); \
            myff[l * FF_ROW + p] = make_uint2(h2u(hh), h2u(ll2));               \
        }                                                                       \
    } while (0)

    // prologue: features for first tile
    PHASE1A(blockIdx.x);
    __syncwarp();

    for (int t = blockIdx.x; t < NT2; t += GRID) {
        const int i  = t >> 2;
        const int jwarp = ((t & 3) << 8) + w * 32;

        // ---- phase 1b: gather A-fragments (8 unconditional LDS.64) ----
        // upper k-pair for lp==3 reads the permanent zero slot (slot 7)
        u32 fh[2][4], fl[2][4];
        #pragma unroll
        for (int s = 0; s < 2; s++) {
            const int r0 = npos + 16 * s;
            uint2 v;
            v = myff[r0 * FF_ROW + lp];
            fh[s][0] = v.x; fl[s][0] = v.y;
            v = myff[(r0 + 8) * FF_ROW + lp];
            fh[s][1] = v.x; fl[s][1] = v.y;
            v = myff[r0 * FF_ROW + lp + 4];
            fh[s][2] = v.x; fl[s][2] = v.y;
            v = myff[(r0 + 8) * FF_ROW + lp + 4];
            fh[s][3] = v.x; fl[s][3] = v.y;
        }

        // ---- phase 1c: GEMM1 on tensor cores, fused ReLU+pack ----
        u32 hL[2][16], hH[2][16];
        #pragma unroll
        for (int gp = 0; gp < 8; gp++) {
            const uint4 wq = *(const uint4*)&W1f2[gp * 128 + 4 * l];
            #pragma unroll
            for (int s = 0; s < 2; s++) {
                float c[4] = {0.f, 0.f, 0.f, 0.f};
                mma16816(c, fh[s][0], fh[s][1], fh[s][2], fh[s][3], wq.x, wq.y);
                mma16816(c, fl[s][0], fl[s][1], fl[s][2], fl[s][3], wq.x, wq.y);
                hL[s][2 * gp]     = hmax2z(h2u(__floats2half2_rn(c[0], c[1])));
                hH[s][2 * gp]     = hmax2z(h2u(__floats2half2_rn(c[2], c[3])));
                float d[4] = {0.f, 0.f, 0.f, 0.f};
                mma16816(d, fh[s][0], fh[s][1], fh[s][2], fh[s][3], wq.z, wq.w);
                mma16816(d, fl[s][0], fl[s][1], fl[s][2], fl[s][3], wq.z, wq.w);
                hL[s][2 * gp + 1] = hmax2z(h2u(__floats2half2_rn(d[0], d[1])));
                hH[s][2 * gp + 1] = hmax2z(h2u(__floats2half2_rn(d[2], d[3])));
            }
        }

        // ---- pipelined phase 1a for tile t+GRID (overlaps phase 2's L1 work) ----
        if (t + GRID < NT2) {
            PHASE1A(t + GRID);
        }
        __syncwarp();   // publish feature table for next iteration's 1b

        // ---- epilogue addressing: fast path unless diagonal in this warp ----
        const int jd = i - jwarp;
        const bool hasdiag = (jd >= 0) && (jd < 32);
        const int jr0 = jwarp + rsub;
        const int orow0 = i * 1023 + jr0 - ((jr0 > i) ? 1 : 0);
        float* const dbase = out + (size_t)orow0 * 128 + colblk;

        // ---- phase 2: GEMM2 via HMMA, 4 passes of 32 cols; staged epilogue ----
        #pragma unroll
        for (int pass = 0; pass < 4; pass++) {
            // acc init = b2 fragments (bias folded into accumulators)
            const float4 i0 = *(const float4*)(myb2f + pass * 256);
            const float4 i1 = *(const float4*)(myb2f + pass * 256 + 4);
            float acc[2][4][4];
            #pragma unroll
            for (int s = 0; s < 2; s++) {
                acc[s][0][0] = i0.x; acc[s][0][1] = i0.y;
                acc[s][0][2] = i0.x; acc[s][0][3] = i0.y;
                acc[s][1][0] = i0.z; acc[s][1][1] = i0.w;
                acc[s][1][2] = i0.z; acc[s][1][3] = i0.w;
                acc[s][2][0] = i1.x; acc[s][2][1] = i1.y;
                acc[s][2][2] = i1.x; acc[s][2][3] = i1.y;
                acc[s][3][0] = i1.z; acc[s][3][1] = i1.w;
                acc[s][3][2] = i1.z; acc[s][3][3] = i1.w;
            }

            const u32* bp = bcombo + pass * 64;
            #pragma unroll
            for (int kt = 0; kt < 8; kt++) {
                const uint4 q0 = *(const uint4*)(bp + kt * 8);      // bv0 nt=0..3
                const uint4 q1 = *(const uint4*)(bp + kt * 8 + 4);  // bv1 nt=0..3
                #pragma unroll
                for (int s = 0; s < 2; s++) {
                    const u32 a0 = hL[s][2 * kt],     a1 = hH[s][2 * kt];
                    const u32 a2 = hL[s][2 * kt + 1], a3 = hH[s][2 * kt + 1];
                    mma16816(acc[s][0], a0, a1, a2, a3, q0.x, q1.x);
                    mma16816(acc[s][1], a0, a1, a2, a3, q0.y, q1.y);
                    mma16816(acc[s][2], a0, a1, a2, a3, q0.z, q1.z);
                    mma16816(acc[s][3], a0, a1, a2, a3, q0.w, q1.w);
                }
            }

            // stage: warp-private buffer, conflict-free STS.64 (row stride 40)
            #pragma unroll
            for (int s = 0; s < 2; s++)
                #pragma unroll
                for (int nt = 0; nt < 4; nt++) {
                    const int colo = nt * 8 + lp * 2;
                    float2 vL = make_float2(acc[s][nt][0], acc[s][nt][1]);
                    float2 vH = make_float2(acc[s][nt][2], acc[s][nt][3]);
                    *(float2*)&mybuf[((2 * s)     * 8 + npos) * STG_ROW + colo] = vL;
                    *(float2*)&mybuf[((2 * s + 1) * 8 + npos) * STG_ROW + colo] = vH;
                }
            __syncwarp();

            // drain: 8 x (LDS.128 + streaming STG.128), full 128B lines
            if (!hasdiag) {
                float* dp = dbase + pass * 32;
                #pragma unroll
                for (int tt = 0; tt < 8; tt++) {
                    float4 v = *(const float4*)&mybuf[(4 * tt + rsub) * STG_ROW + colblk];
                    __stcs((float4*)(dp + tt * 512), v);
                }
            } else {
                #pragma unroll
                for (int tt = 0; tt < 8; tt++) {
                    const int r = 4 * tt + rsub;
                    const int j = jwarp + r;
                    if (j != i) {
                        float4 v = *(const float4*)&mybuf[r * STG_ROW + colblk];
                        const int outrow = i * 1023 + j - ((j > i) ? 1 : 0);
                        __stcs((float4*)(out + (size_t)outrow * 128 + pass * 32 + colblk), v);
                    }
                }
            }
            __syncwarp();
        }
    }
#undef PHASE1A
}

extern "C" void kernel_launch(void* const* d_in, const int* in_sizes, int n_in,
                              void* d_out, int out_size)
{
    const float* boxes = (const float*)d_in[0];
    const float* W1    = (const float*)d_in[1];
    const float* b1    = (const float*)d_in[2];
    const float* W2    = (const float*)d_in[3];
    const float* b2    = (const float*)d_in[4];
    float* out = (float*)d_out;

    cudaFuncSetAttribute(pair_mlp_hmma8,
                         cudaFuncAttributeMaxDynamicSharedMemorySize, SMEM_BYTES);
    pair_mlp_hmma8<<<GRID, 256, SMEM_BYTES>>>(boxes, W1, b1, W2, b2, out);
}